// round 3
// baseline (speedup 1.0000x reference)
#include <cuda_runtime.h>
#include <cuda_bf16.h>

typedef unsigned long long ull;

#define D_C   1024
#define N_B   8
#define N_T   2048
#define M_TOT (N_B * N_T)   // 16384

// ---------------- scratch (static __device__ arrays; no cudaMalloc allowed) ----
__device__ float g_xk[(size_t)M_TOT * D_C];
__device__ float g_xv[(size_t)M_TOT * D_C];
__device__ float g_xr[(size_t)M_TOT * D_C];
__device__ float g_k [(size_t)M_TOT * D_C];
__device__ float g_v [(size_t)M_TOT * D_C];
__device__ float g_r [(size_t)M_TOT * D_C];
__device__ float g_rw[(size_t)M_TOT * D_C];

// ---------------- f32x2 packed-FMA helpers (sm_100+ PTX) ----------------------
__device__ __forceinline__ ull f2fma(ull a, ull b, ull c) {
    ull d;
    asm("fma.rn.f32x2 %0, %1, %2, %3;" : "=l"(d) : "l"(a), "l"(b), "l"(c));
    return d;
}
__device__ __forceinline__ ull f2pack(float lo, float hi) {
    ull d;
    asm("mov.b64 %0, {%1, %2};" : "=l"(d) : "f"(lo), "f"(hi));
    return d;
}
__device__ __forceinline__ ull f2dup(float v) {
    ull d;
    asm("mov.b64 %0, {%1, %1};" : "=l"(d) : "f"(v));
    return d;
}

// ---------------- token-shift mix ---------------------------------------------
// xk = x*tmk + xs*(1-tmk), etc.  One float4 per thread; grid exactly covers.
__global__ void mix_kernel(const float* __restrict__ x,
                           const float* __restrict__ tmk,
                           const float* __restrict__ tmv,
                           const float* __restrict__ tmr) {
    const int C4 = D_C / 4;                       // 256
    int i = blockIdx.x * blockDim.x + threadIdx.x;  // float4 index
    int c4 = i & (C4 - 1);
    int bt = i >> 8;
    int t  = bt & (N_T - 1);

    float4 xc = ((const float4*)x)[i];
    float4 xs = make_float4(0.f, 0.f, 0.f, 0.f);
    if (t > 0) xs = ((const float4*)x)[i - C4];

    float4 mk = ((const float4*)tmk)[c4];
    float4 mv = ((const float4*)tmv)[c4];
    float4 mr = ((const float4*)tmr)[c4];

    float4 ok, ov, orr;
    ok.x = xc.x * mk.x + xs.x * (1.f - mk.x);
    ok.y = xc.y * mk.y + xs.y * (1.f - mk.y);
    ok.z = xc.z * mk.z + xs.z * (1.f - mk.z);
    ok.w = xc.w * mk.w + xs.w * (1.f - mk.w);
    ov.x = xc.x * mv.x + xs.x * (1.f - mv.x);
    ov.y = xc.y * mv.y + xs.y * (1.f - mv.y);
    ov.z = xc.z * mv.z + xs.z * (1.f - mv.z);
    ov.w = xc.w * mv.w + xs.w * (1.f - mv.w);
    orr.x = xc.x * mr.x + xs.x * (1.f - mr.x);
    orr.y = xc.y * mr.y + xs.y * (1.f - mr.y);
    orr.z = xc.z * mr.z + xs.z * (1.f - mr.z);
    orr.w = xc.w * mr.w + xs.w * (1.f - mr.w);

    ((float4*)g_xk)[i] = ok;
    ((float4*)g_xv)[i] = ov;
    ((float4*)g_xr)[i] = orr;
}

// ---------------- fp32 GEMM with packed f32x2 FMA -----------------------------
// C[m,n] = sum_k A[m*K+k] * W[n*K+k]   (A row-major [M,K], W row-major [N,K])
#define BM 128
#define BN 128
#define BK 16

__global__ __launch_bounds__(256, 2)
void sgemm_nt(const float* __restrict__ A, const float* __restrict__ W,
              float* __restrict__ C, int M, int N, int K) {
    __shared__ float As[BK][BM + 4];
    __shared__ float Bs[BK][BN + 4];

    const int tid = threadIdx.x;
    const int bm  = blockIdx.y * BM;
    const int bn  = blockIdx.x * BN;
    const int tx  = tid & 15;      // n-subtile
    const int ty  = tid >> 4;      // m-subtile
    const int lr  = tid >> 2;      // load row 0..63
    const int lc  = (tid & 3) << 2; // load col 0,4,8,12

    ull acc[8][4] = {};            // 8 rows x 4 f32x2 pairs (8 cols)

    const float* Ap = A + (size_t)(bm + lr) * K + lc;
    const float* Wp = W + (size_t)(bn + lr) * K + lc;

    for (int k0 = 0; k0 < K; k0 += BK) {
        float4 a0 = *(const float4*)(Ap);
        float4 a1 = *(const float4*)(Ap + (size_t)64 * K);
        float4 b0 = *(const float4*)(Wp);
        float4 b1 = *(const float4*)(Wp + (size_t)64 * K);
        Ap += BK; Wp += BK;

        __syncthreads();   // previous compute done before overwriting smem
        As[lc + 0][lr] = a0.x; As[lc + 1][lr] = a0.y;
        As[lc + 2][lr] = a0.z; As[lc + 3][lr] = a0.w;
        As[lc + 0][lr + 64] = a1.x; As[lc + 1][lr + 64] = a1.y;
        As[lc + 2][lr + 64] = a1.z; As[lc + 3][lr + 64] = a1.w;
        Bs[lc + 0][lr] = b0.x; Bs[lc + 1][lr] = b0.y;
        Bs[lc + 2][lr] = b0.z; Bs[lc + 3][lr] = b0.w;
        Bs[lc + 0][lr + 64] = b1.x; Bs[lc + 1][lr + 64] = b1.y;
        Bs[lc + 2][lr + 64] = b1.z; Bs[lc + 3][lr + 64] = b1.w;
        __syncthreads();

#pragma unroll
        for (int kk = 0; kk < BK; kk++) {
            // rows: ty*4..+3 and 64+ty*4..+3 ; cols: tx*4..+3 and 64+tx*4..+3
            float4 ra0 = *(const float4*)&As[kk][ty * 4];
            float4 ra1 = *(const float4*)&As[kk][64 + ty * 4];
            float4 rb0 = *(const float4*)&Bs[kk][tx * 4];
            float4 rb1 = *(const float4*)&Bs[kk][64 + tx * 4];

            ull ap[8];
            ap[0] = f2dup(ra0.x); ap[1] = f2dup(ra0.y);
            ap[2] = f2dup(ra0.z); ap[3] = f2dup(ra0.w);
            ap[4] = f2dup(ra1.x); ap[5] = f2dup(ra1.y);
            ap[6] = f2dup(ra1.z); ap[7] = f2dup(ra1.w);
            ull bp[4];
            bp[0] = f2pack(rb0.x, rb0.y); bp[1] = f2pack(rb0.z, rb0.w);
            bp[2] = f2pack(rb1.x, rb1.y); bp[3] = f2pack(rb1.z, rb1.w);

#pragma unroll
            for (int i = 0; i < 8; i++)
#pragma unroll
                for (int j = 0; j < 4; j++)
                    acc[i][j] = f2fma(ap[i], bp[j], acc[i][j]);
        }
    }

    // store: acc[i][j] is cols (base + 2j-within-pair-group)
#pragma unroll
    for (int i = 0; i < 8; i++) {
        int row = bm + ((i < 4) ? (ty * 4 + i) : (64 + ty * 4 + i - 4));
        float* crow = C + (size_t)row * N + bn;
        *(ull*)(crow + tx * 4)          = acc[i][0];
        *(ull*)(crow + tx * 4 + 2)      = acc[i][1];
        *(ull*)(crow + 64 + tx * 4)     = acc[i][2];
        *(ull*)(crow + 64 + tx * 4 + 2) = acc[i][3];
    }
}

// ---------------- WKV scan + sigmoid gate -------------------------------------
// One thread per (b, c). 8192 chains, T=2048 sequential steps.
__global__ void wkv_kernel(const float* __restrict__ w,
                           const float* __restrict__ u) {
    int g = blockIdx.x * blockDim.x + threadIdx.x;  // 0..8191
    int b = g >> 10;
    int c = g & (D_C - 1);

    float wn = -__expf(w[c]);
    float uc = u[c];

    float aa = 0.f, bb = 0.f, pp = -1e38f;
    const float* kp = g_k  + (size_t)b * N_T * D_C + c;
    const float* vp = g_v  + (size_t)b * N_T * D_C + c;
    const float* rp = g_r  + (size_t)b * N_T * D_C + c;
    float*       op = g_rw + (size_t)b * N_T * D_C + c;

    for (int t = 0; t < N_T; t++) {
        float kt = *kp; kp += D_C;
        float vt = *vp; vp += D_C;
        float rt = *rp; rp += D_C;

        float ww = uc + kt;
        float p  = fmaxf(pp, ww);
        float e1 = __expf(pp - p);
        float e2 = __expf(ww - p);
        float y  = (e1 * aa + e2 * vt) / (e1 * bb + e2);

        float sg = 1.f / (1.f + __expf(-rt));
        *op = y * sg; op += D_C;

        float ww2 = pp + wn;
        float p2  = fmaxf(ww2, kt);
        float e1b = __expf(ww2 - p2);
        float e2b = __expf(kt - p2);
        aa = e1b * aa + e2b * vt;
        bb = e1b * bb + e2b;
        pp = p2;
    }
}

// ---------------- launch ------------------------------------------------------
extern "C" void kernel_launch(void* const* d_in, const int* in_sizes, int n_in,
                              void* d_out, int out_size) {
    const float* x   = (const float*)d_in[0];
    const float* w   = (const float*)d_in[1];
    const float* u   = (const float*)d_in[2];
    const float* tmk = (const float*)d_in[3];
    const float* tmv = (const float*)d_in[4];
    const float* tmr = (const float*)d_in[5];
    const float* Wk  = (const float*)d_in[6];
    const float* Wv  = (const float*)d_in[7];
    const float* Wr  = (const float*)d_in[8];
    const float* Wo  = (const float*)d_in[9];
    float* out = (float*)d_out;

    float *xk, *xv, *xr, *k, *v, *r, *rw;
    cudaGetSymbolAddress((void**)&xk, g_xk);
    cudaGetSymbolAddress((void**)&xv, g_xv);
    cudaGetSymbolAddress((void**)&xr, g_xr);
    cudaGetSymbolAddress((void**)&k,  g_k);
    cudaGetSymbolAddress((void**)&v,  g_v);
    cudaGetSymbolAddress((void**)&r,  g_r);
    cudaGetSymbolAddress((void**)&rw, g_rw);

    // 1) token-shift mixes
    mix_kernel<<<(M_TOT * D_C / 4) / 256, 256>>>(x, tmk, tmv, tmr);

    // 2) K/V/R projections
    dim3 gg(D_C / BN, M_TOT / BM);
    sgemm_nt<<<gg, 256>>>(xk, Wk, k, M_TOT, D_C, D_C);
    sgemm_nt<<<gg, 256>>>(xv, Wv, v, M_TOT, D_C, D_C);
    sgemm_nt<<<gg, 256>>>(xr, Wr, r, M_TOT, D_C, D_C);

    // 3) WKV scan fused with sigmoid(r) gate
    wkv_kernel<<<128, 64>>>(w, u);

    // 4) output projection
    sgemm_nt<<<gg, 256>>>(rw, Wo, out, M_TOT, D_C, D_C);
}

// round 5
// speedup vs baseline: 1.9617x; 1.9617x over previous
#include <cuda_runtime.h>
#include <cuda_bf16.h>
#include <stdint.h>

typedef unsigned int u32;
typedef unsigned long long u64;

#define D_C   1024
#define N_T   2048
#define M_TOT 16384   // 8 * 2048

// ---------------- scratch (__device__ globals; no cudaMalloc allowed) ---------
__device__ float g_xk[(size_t)M_TOT * D_C];
__device__ float g_xv[(size_t)M_TOT * D_C];
__device__ float g_xr[(size_t)M_TOT * D_C];
__device__ float g_k [(size_t)M_TOT * D_C];
__device__ float g_v [(size_t)M_TOT * D_C];
__device__ float g_r [(size_t)M_TOT * D_C];
__device__ float g_rw[(size_t)M_TOT * D_C];
__device__ float g_wk[(size_t)D_C * D_C];
__device__ float g_wv[(size_t)D_C * D_C];
__device__ float g_wr[(size_t)D_C * D_C];
__device__ float g_wo[(size_t)D_C * D_C];

// ---------------- PTX helpers (all baseline ISA — no 'a'-suffix features) -----
__device__ __forceinline__ u32 smem_u32(const void* p) {
    u32 a;
    asm("{ .reg .u64 t; cvta.to.shared.u64 t, %1; cvt.u32.u64 %0, t; }"
        : "=r"(a) : "l"(p));
    return a;
}
#define SWZ(o) ((u32)(o) ^ ((((u32)(o)) >> 3) & 0x70))

__device__ __forceinline__ float tf32r(float x) {
    u32 r;
    asm("cvt.rna.tf32.f32 %0, %1;" : "=r"(r) : "f"(x));
    return __uint_as_float(r);
}

__device__ __forceinline__ void cpasync16(u32 s, const void* g) {
    asm volatile("cp.async.cg.shared.global [%0], [%1], 16;" :: "r"(s), "l"(g));
}
#define CP_COMMIT asm volatile("cp.async.commit_group;" ::: "memory")
#define CP_WAIT1  asm volatile("cp.async.wait_group 1;" ::: "memory")
#define CP_WAIT0  asm volatile("cp.async.wait_group 0;" ::: "memory")

__device__ __forceinline__ void ldsm4(u32& r0, u32& r1, u32& r2, u32& r3, u32 a) {
    asm volatile("ldmatrix.sync.aligned.m8n8.x4.shared.b16 {%0,%1,%2,%3}, [%4];"
                 : "=r"(r0), "=r"(r1), "=r"(r2), "=r"(r3) : "r"(a));
}

__device__ __forceinline__ void mma_tf32(float* d, u32 a0, u32 a1, u32 a2, u32 a3,
                                         u32 b0, u32 b1) {
    asm volatile(
        "mma.sync.aligned.m16n8k8.row.col.f32.tf32.tf32.f32 "
        "{%0,%1,%2,%3},{%4,%5,%6,%7},{%8,%9},{%0,%1,%2,%3};"
        : "+f"(d[0]), "+f"(d[1]), "+f"(d[2]), "+f"(d[3])
        : "r"(a0), "r"(a1), "r"(a2), "r"(a3), "r"(b0), "r"(b1));
}

// ---------------- weight convert: fp32 -> tf32-rounded fp32 -------------------
__global__ void wconv_kernel(const float4* __restrict__ W, float4* __restrict__ O) {
    int i = blockIdx.x * blockDim.x + threadIdx.x;   // 0..262143
    float4 v = W[i];
    O[i] = make_float4(tf32r(v.x), tf32r(v.y), tf32r(v.z), tf32r(v.w));
}

// ---------------- token-shift mix -> tf32-rounded fp32 ------------------------
__global__ void mix_kernel(const float* __restrict__ x,
                           const float* __restrict__ tmk,
                           const float* __restrict__ tmv,
                           const float* __restrict__ tmr) {
    const int C4 = D_C / 4;                         // 256
    int i = blockIdx.x * blockDim.x + threadIdx.x;  // float4 index
    int c4 = i & (C4 - 1);
    int bt = i >> 8;
    int t  = bt & (N_T - 1);

    float4 xc = ((const float4*)x)[i];
    float4 xs = make_float4(0.f, 0.f, 0.f, 0.f);
    if (t > 0) xs = ((const float4*)x)[i - C4];

    float4 mk = ((const float4*)tmk)[c4];
    float4 mv = ((const float4*)tmv)[c4];
    float4 mr = ((const float4*)tmr)[c4];

    float4 ok, ov, orr;
    ok.x = tf32r(xc.x * mk.x + xs.x * (1.f - mk.x));
    ok.y = tf32r(xc.y * mk.y + xs.y * (1.f - mk.y));
    ok.z = tf32r(xc.z * mk.z + xs.z * (1.f - mk.z));
    ok.w = tf32r(xc.w * mk.w + xs.w * (1.f - mk.w));
    ov.x = tf32r(xc.x * mv.x + xs.x * (1.f - mv.x));
    ov.y = tf32r(xc.y * mv.y + xs.y * (1.f - mv.y));
    ov.z = tf32r(xc.z * mv.z + xs.z * (1.f - mv.z));
    ov.w = tf32r(xc.w * mv.w + xs.w * (1.f - mv.w));
    orr.x = tf32r(xc.x * mr.x + xs.x * (1.f - mr.x));
    orr.y = tf32r(xc.y * mr.y + xs.y * (1.f - mr.y));
    orr.z = tf32r(xc.z * mr.z + xs.z * (1.f - mr.z));
    orr.w = tf32r(xc.w * mr.w + xs.w * (1.f - mr.w));

    ((float4*)g_xk)[i] = ok;
    ((float4*)g_xv)[i] = ov;
    ((float4*)g_xr)[i] = orr;
}

// ---------------- tf32 mma.sync GEMM ------------------------------------------
// C[m,n] = sum_k A[m,k]*W[n,k]; A [M,1024], W [1024,1024], both tf32-pre-rounded.
// CTA 128x128, BK=32 floats (one 128B SW128 row), 4 warps of 64x64, cp.async x2.
#define GBM 128
#define GBN 128
#define STG 32768                 // per-stage bytes: A 16K + B 16K
#define GSMEM (2 * STG)           // 64 KB

__global__ __launch_bounds__(128, 2)
void gemm_tf32(const float* __restrict__ A, const float* __restrict__ W,
               float* __restrict__ C) {
    extern __shared__ char smem[];
    u32 sb = smem_u32(smem);
    const int tid = threadIdx.x, lane = tid & 31, wid = tid >> 5;
    const int bm = blockIdx.y * GBM, bn = blockIdx.x * GBN;
    const int mband = (wid >> 1) * 64, nband = (wid & 1) * 64;

    // ldmatrix lane-constant address components
    const int arow = ((lane >> 3) & 1) * 8 + (lane & 7);
    const int acg  = (lane >> 4) * 16;          // byte offset within 32B k-step
    const int brow = ((lane >> 4) & 1) * 8 + (lane & 7);
    const int bcg  = ((lane >> 3) & 1) * 16;

    float acc[4][8][4];
#pragma unroll
    for (int i = 0; i < 4; i++)
#pragma unroll
        for (int j = 0; j < 8; j++)
#pragma unroll
            for (int q = 0; q < 4; q++) acc[i][j][q] = 0.f;

    const float* Ag = A + (size_t)bm * D_C;
    const float* Wg = W + (size_t)bn * D_C;

    // ---- producer: stage kt -> smem buffer (kt&1) via cp.async ----
#define ISSUE(kt)                                                              \
    {                                                                          \
        u32 st = sb + (((kt) & 1) ? STG : 0);                                  \
        int koff = (kt) * 32;                                                  \
        _Pragma("unroll")                                                      \
        for (int ii = 0; ii < 8; ii++) {                                       \
            int g = tid + (ii << 7);                                           \
            int row = g >> 3, c4 = g & 7;                                      \
            u32 so = SWZ(row * 128 + c4 * 16);                                 \
            cpasync16(st + so,         Ag + (size_t)row * D_C + koff + c4 * 4);\
            cpasync16(st + 16384 + so, Wg + (size_t)row * D_C + koff + c4 * 4);\
        }                                                                      \
        CP_COMMIT;                                                             \
    }

    ISSUE(0);
    for (int kt = 0; kt < 32; kt++) {
        if (kt < 31) { ISSUE(kt + 1); CP_WAIT1; }
        else         { CP_WAIT0; }
        __syncthreads();

        u32 aB = sb + ((kt & 1) ? STG : 0);
        u32 bB = aB + 16384;
#pragma unroll
        for (int s = 0; s < 4; s++) {
            u32 af[4][4];
#pragma unroll
            for (int i = 0; i < 4; i++) {
                u32 addr = aB + SWZ((mband + 16 * i + arow) * 128 + s * 32 + acg);
                ldsm4(af[i][0], af[i][1], af[i][2], af[i][3], addr);
            }
#pragma unroll
            for (int jp = 0; jp < 4; jp++) {
                u32 b0, b1, b2, b3;
                u32 addr = bB + SWZ((nband + 16 * jp + brow) * 128 + s * 32 + bcg);
                ldsm4(b0, b1, b2, b3, addr);
#pragma unroll
                for (int i = 0; i < 4; i++) {
                    mma_tf32(acc[i][2 * jp],     af[i][0], af[i][1], af[i][2], af[i][3], b0, b1);
                    mma_tf32(acc[i][2 * jp + 1], af[i][0], af[i][1], af[i][2], af[i][3], b2, b3);
                }
            }
        }
        __syncthreads();
    }

    // ---- epilogue: direct float2 stores ----
#pragma unroll
    for (int i = 0; i < 4; i++) {
        int row = bm + mband + 16 * i + (lane >> 2);
#pragma unroll
        for (int j = 0; j < 8; j++) {
            int col = bn + nband + 8 * j + 2 * (lane & 3);
            *(float2*)&C[(size_t)row * D_C + col] =
                make_float2(acc[i][j][0], acc[i][j][1]);
            *(float2*)&C[(size_t)(row + 8) * D_C + col] =
                make_float2(acc[i][j][2], acc[i][j][3]);
        }
    }
}

// ---------------- WKV scan + sigmoid gate (prefetched, unroll 8) --------------
__global__ void wkv_kernel(const float* __restrict__ w,
                           const float* __restrict__ u) {
    int g = blockIdx.x * blockDim.x + threadIdx.x;  // 0..8191
    int b = g >> 10;
    int c = g & (D_C - 1);

    float wn = -__expf(w[c]);
    float uc = u[c];
    float aa = 0.f, bb = 0.f, pp = -1e38f;

    size_t base = (size_t)b * N_T * D_C + c;
    const float* kp = g_k + base;
    const float* vp = g_v + base;
    const float* rp = g_r + base;
    float*       op = g_rw + base;

    float kB[2][8], vB[2][8], rB[2][8];
#pragma unroll
    for (int j = 0; j < 8; j++) {
        kB[0][j] = kp[(size_t)j * D_C];
        vB[0][j] = vp[(size_t)j * D_C];
        rB[0][j] = rp[(size_t)j * D_C];
    }
    int cur = 0;
    for (int t0 = 0; t0 < N_T; t0 += 8) {
        int nxt = cur ^ 1;
        if (t0 + 8 < N_T) {
            size_t off = (size_t)(t0 + 8) * D_C;
#pragma unroll
            for (int j = 0; j < 8; j++) {
                kB[nxt][j] = kp[off + (size_t)j * D_C];
                vB[nxt][j] = vp[off + (size_t)j * D_C];
                rB[nxt][j] = rp[off + (size_t)j * D_C];
            }
        }
#pragma unroll
        for (int j = 0; j < 8; j++) {
            float kt = kB[cur][j], vt = vB[cur][j], rt = rB[cur][j];

            float ww = uc + kt;
            float p  = fmaxf(pp, ww);
            float e1 = __expf(pp - p);
            float e2 = __expf(ww - p);
            float y  = (e1 * aa + e2 * vt) / (e1 * bb + e2);

            float sg  = 1.f / (1.f + __expf(-rt));
            op[(size_t)(t0 + j) * D_C] = tf32r(y * sg);

            float ww2 = pp + wn;
            float p2  = fmaxf(ww2, kt);
            float e1b = __expf(ww2 - p2);
            float e2b = __expf(kt - p2);
            aa = e1b * aa + e2b * vt;
            bb = e1b * bb + e2b;
            pp = p2;
        }
        cur = nxt;
    }
}

// ---------------- launch ------------------------------------------------------
extern "C" void kernel_launch(void* const* d_in, const int* in_sizes, int n_in,
                              void* d_out, int out_size) {
    const float* x   = (const float*)d_in[0];
    const float* w   = (const float*)d_in[1];
    const float* u   = (const float*)d_in[2];
    const float* tmk = (const float*)d_in[3];
    const float* tmv = (const float*)d_in[4];
    const float* tmr = (const float*)d_in[5];
    const float* Wk  = (const float*)d_in[6];
    const float* Wv  = (const float*)d_in[7];
    const float* Wr  = (const float*)d_in[8];
    const float* Wo  = (const float*)d_in[9];
    float* out = (float*)d_out;

    float *xk, *xv, *xr, *k, *v, *r, *rw, *wk, *wv, *wr, *wo;
    cudaGetSymbolAddress((void**)&xk, g_xk);
    cudaGetSymbolAddress((void**)&xv, g_xv);
    cudaGetSymbolAddress((void**)&xr, g_xr);
    cudaGetSymbolAddress((void**)&k,  g_k);
    cudaGetSymbolAddress((void**)&v,  g_v);
    cudaGetSymbolAddress((void**)&r,  g_r);
    cudaGetSymbolAddress((void**)&rw, g_rw);
    cudaGetSymbolAddress((void**)&wk, g_wk);
    cudaGetSymbolAddress((void**)&wv, g_wv);
    cudaGetSymbolAddress((void**)&wr, g_wr);
    cudaGetSymbolAddress((void**)&wo, g_wo);

    cudaFuncSetAttribute(gemm_tf32,
                         cudaFuncAttributeMaxDynamicSharedMemorySize, GSMEM);

    // 1) tf32-round weights + mixed activations
    wconv_kernel<<<1024, 256>>>((const float4*)Wk, (float4*)wk);
    wconv_kernel<<<1024, 256>>>((const float4*)Wv, (float4*)wv);
    wconv_kernel<<<1024, 256>>>((const float4*)Wr, (float4*)wr);
    wconv_kernel<<<1024, 256>>>((const float4*)Wo, (float4*)wo);
    mix_kernel<<<(M_TOT * D_C / 4) / 256, 256>>>(x, tmk, tmv, tmr);

    // 2) K/V/R projections (tf32 tensor-core mma.sync)
    dim3 gg(D_C / GBN, M_TOT / GBM);   // (8, 128)
    gemm_tf32<<<gg, 128, GSMEM>>>(xk, wk, k);
    gemm_tf32<<<gg, 128, GSMEM>>>(xv, wv, v);
    gemm_tf32<<<gg, 128, GSMEM>>>(xr, wr, r);

    // 3) WKV scan + sigmoid gate
    wkv_kernel<<<128, 64>>>(w, u);

    // 4) output projection
    gemm_tf32<<<gg, 128, GSMEM>>>(rw, wo, out);
}

// round 6
// speedup vs baseline: 4.2110x; 2.1466x over previous
#include <cuda_runtime.h>
#include <cuda_fp16.h>
#include <stdint.h>

typedef unsigned int u32;
typedef unsigned long long u64;

#define D_C   1024
#define N_T   2048
#define M_TOT 16384   // 8 * 2048

// ---------------- scratch (__device__ globals; no cudaMalloc allowed) ---------
__device__ __half g_xk[(size_t)M_TOT * D_C];
__device__ __half g_xv[(size_t)M_TOT * D_C];
__device__ __half g_xr[(size_t)M_TOT * D_C];
__device__ __half g_rw[(size_t)M_TOT * D_C];
__device__ float  g_k [(size_t)M_TOT * D_C];
__device__ float  g_v [(size_t)M_TOT * D_C];
__device__ float  g_r [(size_t)M_TOT * D_C];
__device__ __half g_wk[(size_t)D_C * D_C];
__device__ __half g_wv[(size_t)D_C * D_C];
__device__ __half g_wr[(size_t)D_C * D_C];
__device__ __half g_wo[(size_t)D_C * D_C];

// ---------------- PTX helpers (baseline ISA only — no 'a'-suffix features) ----
__device__ __forceinline__ u32 smem_u32(const void* p) {
    u32 a;
    asm("{ .reg .u64 t; cvta.to.shared.u64 t, %1; cvt.u32.u64 %0, t; }"
        : "=r"(a) : "l"(p));
    return a;
}
#define SWZ(o) ((u32)(o) ^ ((((u32)(o)) >> 3) & 0x70))

__device__ __forceinline__ void cpasync16(u32 s, const void* g) {
    asm volatile("cp.async.cg.shared.global [%0], [%1], 16;" :: "r"(s), "l"(g));
}
#define CP_COMMIT asm volatile("cp.async.commit_group;" ::: "memory")
#define CP_WAIT1  asm volatile("cp.async.wait_group 1;" ::: "memory")
#define CP_WAIT0  asm volatile("cp.async.wait_group 0;" ::: "memory")

__device__ __forceinline__ void ldsm4(u32& r0, u32& r1, u32& r2, u32& r3, u32 a) {
    asm volatile("ldmatrix.sync.aligned.m8n8.x4.shared.b16 {%0,%1,%2,%3}, [%4];"
                 : "=r"(r0), "=r"(r1), "=r"(r2), "=r"(r3) : "r"(a));
}

__device__ __forceinline__ void mma_f16(float* d, u32 a0, u32 a1, u32 a2, u32 a3,
                                        u32 b0, u32 b1) {
    asm volatile(
        "mma.sync.aligned.m16n8k16.row.col.f32.f16.f16.f32 "
        "{%0,%1,%2,%3},{%4,%5,%6,%7},{%8,%9},{%0,%1,%2,%3};"
        : "+f"(d[0]), "+f"(d[1]), "+f"(d[2]), "+f"(d[3])
        : "r"(a0), "r"(a1), "r"(a2), "r"(a3), "r"(b0), "r"(b1));
}

__device__ __forceinline__ u32 pack_h2(float lo, float hi) {
    __half2 h = __floats2half2_rn(lo, hi);
    return *(u32*)&h;
}

// ---------------- weight convert: 4 matrices fp32 -> fp16, one launch ---------
__global__ void wconv_kernel(const float4* __restrict__ W0, __half* __restrict__ O0,
                             const float4* __restrict__ W1, __half* __restrict__ O1,
                             const float4* __restrict__ W2, __half* __restrict__ O2,
                             const float4* __restrict__ W3, __half* __restrict__ O3) {
    int i = blockIdx.x * blockDim.x + threadIdx.x;   // 0..262143
    const float4* W = (blockIdx.y == 0) ? W0 : (blockIdx.y == 1) ? W1
                    : (blockIdx.y == 2) ? W2 : W3;
    __half* O = (blockIdx.y == 0) ? O0 : (blockIdx.y == 1) ? O1
              : (blockIdx.y == 2) ? O2 : O3;
    float4 v = W[i];
    ((uint2*)O)[i] = make_uint2(pack_h2(v.x, v.y), pack_h2(v.z, v.w));
}

// ---------------- token-shift mix -> fp16 -------------------------------------
__global__ void mix_kernel(const float* __restrict__ x,
                           const float* __restrict__ tmk,
                           const float* __restrict__ tmv,
                           const float* __restrict__ tmr) {
    const int C4 = D_C / 4;                         // 256
    int i = blockIdx.x * blockDim.x + threadIdx.x;  // float4 index
    int c4 = i & (C4 - 1);
    int bt = i >> 8;
    int t  = bt & (N_T - 1);

    float4 xc = ((const float4*)x)[i];
    float4 xs = make_float4(0.f, 0.f, 0.f, 0.f);
    if (t > 0) xs = ((const float4*)x)[i - C4];

    float4 mk = ((const float4*)tmk)[c4];
    float4 mv = ((const float4*)tmv)[c4];
    float4 mr = ((const float4*)tmr)[c4];

    float kx = xc.x * mk.x + xs.x * (1.f - mk.x);
    float ky = xc.y * mk.y + xs.y * (1.f - mk.y);
    float kz = xc.z * mk.z + xs.z * (1.f - mk.z);
    float kw = xc.w * mk.w + xs.w * (1.f - mk.w);
    float vx = xc.x * mv.x + xs.x * (1.f - mv.x);
    float vy = xc.y * mv.y + xs.y * (1.f - mv.y);
    float vz = xc.z * mv.z + xs.z * (1.f - mv.z);
    float vw = xc.w * mv.w + xs.w * (1.f - mv.w);
    float rx = xc.x * mr.x + xs.x * (1.f - mr.x);
    float ry = xc.y * mr.y + xs.y * (1.f - mr.y);
    float rz = xc.z * mr.z + xs.z * (1.f - mr.z);
    float rw = xc.w * mr.w + xs.w * (1.f - mr.w);

    ((uint2*)g_xk)[i] = make_uint2(pack_h2(kx, ky), pack_h2(kz, kw));
    ((uint2*)g_xv)[i] = make_uint2(pack_h2(vx, vy), pack_h2(vz, vw));
    ((uint2*)g_xr)[i] = make_uint2(pack_h2(rx, ry), pack_h2(rz, rw));
}

// ---------------- fp16 mma.sync GEMM ------------------------------------------
// C[m,n] = sum_k A[m,k]*W[n,k]; fp16 inputs, fp32 accumulate/output.
// CTA 128x128, BK=64 halves (one 128B SW128 row), 4 warps of 64x64, cp.async x2.
#define GBM 128
#define GBN 128
#define STG 32768                 // per-stage bytes: A 16K + B 16K
#define GSMEM (2 * STG)           // 64 KB

__global__ __launch_bounds__(128, 2)
void gemm_f16(const __half* __restrict__ A, const __half* __restrict__ W,
              float* __restrict__ C) {
    extern __shared__ char smem[];
    u32 sb = smem_u32(smem);
    const int tid = threadIdx.x, lane = tid & 31, wid = tid >> 5;
    const int bm = blockIdx.y * GBM, bn = blockIdx.x * GBN;
    const int mband = (wid >> 1) * 64, nband = (wid & 1) * 64;

    // ldmatrix lane-address components
    const int arow = lane & 15;
    const int acg  = (lane >> 4) * 16;           // A byte col within 32B k-step
    const int brow = ((lane >> 4) & 1) * 8 + (lane & 7);
    const int bcg  = ((lane >> 3) & 1) * 16;

    float acc[4][8][4];
#pragma unroll
    for (int i = 0; i < 4; i++)
#pragma unroll
        for (int j = 0; j < 8; j++)
#pragma unroll
            for (int q = 0; q < 4; q++) acc[i][j][q] = 0.f;

    const __half* Ag = A + (size_t)bm * D_C;
    const __half* Wg = W + (size_t)bn * D_C;

    // stage kt -> smem buffer (kt&1): 128 rows x 64 halves each for A and B
#define ISSUE(kt)                                                              \
    {                                                                          \
        u32 st = sb + (((kt) & 1) ? STG : 0);                                  \
        int koff = (kt) * 64;                                                  \
        _Pragma("unroll")                                                      \
        for (int ii = 0; ii < 8; ii++) {                                       \
            int g = tid + (ii << 7);                                           \
            int row = g >> 3, c8 = g & 7;                                      \
            u32 so = SWZ(row * 128 + c8 * 16);                                 \
            cpasync16(st + so,         Ag + (size_t)row * D_C + koff + c8 * 8);\
            cpasync16(st + 16384 + so, Wg + (size_t)row * D_C + koff + c8 * 8);\
        }                                                                      \
        CP_COMMIT;                                                             \
    }

    ISSUE(0);
    for (int kt = 0; kt < 16; kt++) {
        if (kt < 15) { ISSUE(kt + 1); CP_WAIT1; }
        else         { CP_WAIT0; }
        __syncthreads();

        u32 aB = sb + ((kt & 1) ? STG : 0);
        u32 bB = aB + 16384;
#pragma unroll
        for (int s = 0; s < 4; s++) {              // 4 k-steps of 16
            u32 af[4][4];
#pragma unroll
            for (int i = 0; i < 4; i++) {
                u32 addr = aB + SWZ((mband + 16 * i + arow) * 128 + s * 32 + acg);
                ldsm4(af[i][0], af[i][1], af[i][2], af[i][3], addr);
            }
#pragma unroll
            for (int jp = 0; jp < 4; jp++) {       // pairs of 8-wide n tiles
                u32 b0, b1, b2, b3;
                u32 addr = bB + SWZ((nband + 16 * jp + brow) * 128 + s * 32 + bcg);
                ldsm4(b0, b1, b2, b3, addr);
#pragma unroll
                for (int i = 0; i < 4; i++) {
                    mma_f16(acc[i][2 * jp],     af[i][0], af[i][1], af[i][2], af[i][3], b0, b1);
                    mma_f16(acc[i][2 * jp + 1], af[i][0], af[i][1], af[i][2], af[i][3], b2, b3);
                }
            }
        }
        __syncthreads();
    }

    // epilogue: direct float2 stores
#pragma unroll
    for (int i = 0; i < 4; i++) {
        int row = bm + mband + 16 * i + (lane >> 2);
#pragma unroll
        for (int j = 0; j < 8; j++) {
            int col = bn + nband + 8 * j + 2 * (lane & 3);
            *(float2*)&C[(size_t)row * D_C + col] =
                make_float2(acc[i][j][0], acc[i][j][1]);
            *(float2*)&C[(size_t)(row + 8) * D_C + col] =
                make_float2(acc[i][j][2], acc[i][j][3]);
        }
    }
}

// ---------------- WKV scan + sigmoid gate (prefetched, unroll 16) -------------
#define UNR 16
__global__ void wkv_kernel(const float* __restrict__ w,
                           const float* __restrict__ u) {
    int g = blockIdx.x * blockDim.x + threadIdx.x;  // 0..8191
    int b = g >> 10;
    int c = g & (D_C - 1);

    float wn = -__expf(w[c]);
    float uc = u[c];
    float aa = 0.f, bb = 0.f, pp = -1e38f;

    size_t base = (size_t)b * N_T * D_C + c;
    const float* kp = g_k + base;
    const float* vp = g_v + base;
    const float* rp = g_r + base;
    __half*      op = g_rw + base;

    float kB[2][UNR], vB[2][UNR], rB[2][UNR];
#pragma unroll
    for (int j = 0; j < UNR; j++) {
        kB[0][j] = kp[(size_t)j * D_C];
        vB[0][j] = vp[(size_t)j * D_C];
        rB[0][j] = rp[(size_t)j * D_C];
    }
    int cur = 0;
    for (int t0 = 0; t0 < N_T; t0 += UNR) {
        int nxt = cur ^ 1;
        if (t0 + UNR < N_T) {
            size_t off = (size_t)(t0 + UNR) * D_C;
#pragma unroll
            for (int j = 0; j < UNR; j++) {
                kB[nxt][j] = kp[off + (size_t)j * D_C];
                vB[nxt][j] = vp[off + (size_t)j * D_C];
                rB[nxt][j] = rp[off + (size_t)j * D_C];
            }
        }
#pragma unroll
        for (int j = 0; j < UNR; j++) {
            float kt = kB[cur][j], vt = vB[cur][j], rt = rB[cur][j];

            float ww = uc + kt;
            float p  = fmaxf(pp, ww);
            float e1 = __expf(pp - p);
            float e2 = __expf(ww - p);
            float y  = (e1 * aa + e2 * vt) / (e1 * bb + e2);

            float sg = 1.f / (1.f + __expf(-rt));
            op[(size_t)(t0 + j) * D_C] = __float2half_rn(y * sg);

            float ww2 = pp + wn;
            float p2  = fmaxf(ww2, kt);
            float e1b = __expf(ww2 - p2);
            float e2b = __expf(kt - p2);
            aa = e1b * aa + e2b * vt;
            bb = e1b * bb + e2b;
            pp = p2;
        }
        cur = nxt;
    }
}

// ---------------- launch ------------------------------------------------------
extern "C" void kernel_launch(void* const* d_in, const int* in_sizes, int n_in,
                              void* d_out, int out_size) {
    const float* x   = (const float*)d_in[0];
    const float* w   = (const float*)d_in[1];
    const float* u   = (const float*)d_in[2];
    const float* tmk = (const float*)d_in[3];
    const float* tmv = (const float*)d_in[4];
    const float* tmr = (const float*)d_in[5];
    const float* Wk  = (const float*)d_in[6];
    const float* Wv  = (const float*)d_in[7];
    const float* Wr  = (const float*)d_in[8];
    const float* Wo  = (const float*)d_in[9];
    float* out = (float*)d_out;

    __half *xk, *xv, *xr, *rw, *wk, *wv, *wr, *wo;
    float *k, *v, *r;
    cudaGetSymbolAddress((void**)&xk, g_xk);
    cudaGetSymbolAddress((void**)&xv, g_xv);
    cudaGetSymbolAddress((void**)&xr, g_xr);
    cudaGetSymbolAddress((void**)&rw, g_rw);
    cudaGetSymbolAddress((void**)&wk, g_wk);
    cudaGetSymbolAddress((void**)&wv, g_wv);
    cudaGetSymbolAddress((void**)&wr, g_wr);
    cudaGetSymbolAddress((void**)&wo, g_wo);
    cudaGetSymbolAddress((void**)&k,  g_k);
    cudaGetSymbolAddress((void**)&v,  g_v);
    cudaGetSymbolAddress((void**)&r,  g_r);

    cudaFuncSetAttribute(gemm_f16,
                         cudaFuncAttributeMaxDynamicSharedMemorySize, GSMEM);

    // 1) fp16 weights (one launch) + mixed activations
    wconv_kernel<<<dim3(1024, 4), 256>>>((const float4*)Wk, wk,
                                         (const float4*)Wv, wv,
                                         (const float4*)Wr, wr,
                                         (const float4*)Wo, wo);
    mix_kernel<<<(M_TOT * D_C / 4) / 256, 256>>>(x, tmk, tmv, tmr);

    // 2) K/V/R projections (fp16 tensor-core mma.sync, fp32 out)
    dim3 gg(D_C / GBN, M_TOT / GBM);   // (8, 128)
    gemm_f16<<<gg, 128, GSMEM>>>(xk, wk, k);
    gemm_f16<<<gg, 128, GSMEM>>>(xv, wv, v);
    gemm_f16<<<gg, 128, GSMEM>>>(xr, wr, r);

    // 3) WKV scan + sigmoid gate (emits fp16 for the output GEMM)
    wkv_kernel<<<128, 64>>>(w, u);

    // 4) output projection
    gemm_f16<<<gg, 128, GSMEM>>>(rw, wo, out);
}

// round 10
// speedup vs baseline: 8.0664x; 1.9156x over previous
#include <cuda_runtime.h>
#include <cuda_fp16.h>
#include <stdint.h>

typedef unsigned int u32;
typedef unsigned long long u64;

#define D_C   1024
#define N_T   2048
#define M_TOT 16384   // 8 * 2048
#define NCH   8192    // B * D_C chains
#define SCH   16      // scan chunks
#define LCH   128     // tokens per chunk (SCH*LCH = N_T)

// ---------------- scratch (__device__ globals; no cudaMalloc allowed) ---------
__device__ __half g_xk[(size_t)M_TOT * D_C];
__device__ __half g_xv[(size_t)M_TOT * D_C];
__device__ __half g_xr[(size_t)M_TOT * D_C];
__device__ __half g_rw[(size_t)M_TOT * D_C];
__device__ float  g_k [(size_t)M_TOT * D_C];
__device__ float  g_v [(size_t)M_TOT * D_C];
__device__ float  g_r [(size_t)M_TOT * D_C];
__device__ __half g_wk[(size_t)D_C * D_C];
__device__ __half g_wv[(size_t)D_C * D_C];
__device__ __half g_wr[(size_t)D_C * D_C];
__device__ __half g_wo[(size_t)D_C * D_C];
// chunked-scan state: [SCH][NCH]
__device__ float g_saa[SCH * NCH], g_sbb[SCH * NCH], g_spp[SCH * NCH];
__device__ float g_iaa[SCH * NCH], g_ibb[SCH * NCH], g_ipp[SCH * NCH];

// ---------------- PTX helpers (baseline ISA only) ------------------------------
__device__ __forceinline__ u32 smem_u32(const void* p) {
    u32 a;
    asm("{ .reg .u64 t; cvta.to.shared.u64 t, %1; cvt.u32.u64 %0, t; }"
        : "=r"(a) : "l"(p));
    return a;
}
#define SWZ(o) ((u32)(o) ^ ((((u32)(o)) >> 3) & 0x70))

__device__ __forceinline__ void cpasync16(u32 s, const void* g) {
    asm volatile("cp.async.cg.shared.global [%0], [%1], 16;" :: "r"(s), "l"(g));
}
#define CP_COMMIT asm volatile("cp.async.commit_group;" ::: "memory")
#define CP_WAIT1  asm volatile("cp.async.wait_group 1;" ::: "memory")
#define CP_WAIT0  asm volatile("cp.async.wait_group 0;" ::: "memory")

__device__ __forceinline__ void ldsm4(u32& r0, u32& r1, u32& r2, u32& r3, u32 a) {
    asm volatile("ldmatrix.sync.aligned.m8n8.x4.shared.b16 {%0,%1,%2,%3}, [%4];"
                 : "=r"(r0), "=r"(r1), "=r"(r2), "=r"(r3) : "r"(a));
}

__device__ __forceinline__ void mma_f16(float* d, u32 a0, u32 a1, u32 a2, u32 a3,
                                        u32 b0, u32 b1) {
    asm volatile(
        "mma.sync.aligned.m16n8k16.row.col.f32.f16.f16.f32 "
        "{%0,%1,%2,%3},{%4,%5,%6,%7},{%8,%9},{%0,%1,%2,%3};"
        : "+f"(d[0]), "+f"(d[1]), "+f"(d[2]), "+f"(d[3])
        : "r"(a0), "r"(a1), "r"(a2), "r"(a3), "r"(b0), "r"(b1));
}

__device__ __forceinline__ u32 pack_h2(float lo, float hi) {
    __half2 h = __floats2half2_rn(lo, hi);
    return *(u32*)&h;
}

// ---------------- weight convert: 4 matrices fp32 -> fp16, one launch ---------
__global__ void wconv_kernel(const float4* __restrict__ W0, __half* __restrict__ O0,
                             const float4* __restrict__ W1, __half* __restrict__ O1,
                             const float4* __restrict__ W2, __half* __restrict__ O2,
                             const float4* __restrict__ W3, __half* __restrict__ O3) {
    int i = blockIdx.x * blockDim.x + threadIdx.x;
    const float4* W = (blockIdx.y == 0) ? W0 : (blockIdx.y == 1) ? W1
                    : (blockIdx.y == 2) ? W2 : W3;
    __half* O = (blockIdx.y == 0) ? O0 : (blockIdx.y == 1) ? O1
              : (blockIdx.y == 2) ? O2 : O3;
    float4 v = W[i];
    ((uint2*)O)[i] = make_uint2(pack_h2(v.x, v.y), pack_h2(v.z, v.w));
}

// ---------------- token-shift mix -> fp16 -------------------------------------
__global__ void mix_kernel(const float* __restrict__ x,
                           const float* __restrict__ tmk,
                           const float* __restrict__ tmv,
                           const float* __restrict__ tmr) {
    const int C4 = D_C / 4;
    int i = blockIdx.x * blockDim.x + threadIdx.x;
    int c4 = i & (C4 - 1);
    int bt = i >> 8;
    int t  = bt & (N_T - 1);

    float4 xc = ((const float4*)x)[i];
    float4 xs = make_float4(0.f, 0.f, 0.f, 0.f);
    if (t > 0) xs = ((const float4*)x)[i - C4];

    float4 mk = ((const float4*)tmk)[c4];
    float4 mv = ((const float4*)tmv)[c4];
    float4 mr = ((const float4*)tmr)[c4];

    float kx = xc.x * mk.x + xs.x * (1.f - mk.x);
    float ky = xc.y * mk.y + xs.y * (1.f - mk.y);
    float kz = xc.z * mk.z + xs.z * (1.f - mk.z);
    float kw = xc.w * mk.w + xs.w * (1.f - mk.w);
    float vx = xc.x * mv.x + xs.x * (1.f - mv.x);
    float vy = xc.y * mv.y + xs.y * (1.f - mv.y);
    float vz = xc.z * mv.z + xs.z * (1.f - mv.z);
    float vw = xc.w * mv.w + xs.w * (1.f - mv.w);
    float rx = xc.x * mr.x + xs.x * (1.f - mr.x);
    float ry = xc.y * mr.y + xs.y * (1.f - mr.y);
    float rz = xc.z * mr.z + xs.z * (1.f - mr.z);
    float rw = xc.w * mr.w + xs.w * (1.f - mr.w);

    ((uint2*)g_xk)[i] = make_uint2(pack_h2(kx, ky), pack_h2(kz, kw));
    ((uint2*)g_xv)[i] = make_uint2(pack_h2(vx, vy), pack_h2(vz, vw));
    ((uint2*)g_xr)[i] = make_uint2(pack_h2(rx, ry), pack_h2(rz, rw));
}

// ---------------- fp16 mma.sync GEMM (3-stage pipeline, z-batched) -------------
// C[m,n] = sum_k A[m,k]*W[n,k]; fp16 in, fp32 out. CTA 128x128, BK=64,
// 3-stage cp.async, one __syncthreads per k-iter. blockIdx.z picks matrix set.
#define GBM 128
#define GBN 128
#define STG 32768                 // per-stage bytes: A 16K + B 16K
#define GSMEM (3 * STG)           // 96 KB

__global__ __launch_bounds__(128, 2)
void gemm_f16(const __half* __restrict__ A0, const __half* __restrict__ W0,
              float* __restrict__ C0,
              const __half* __restrict__ A1, const __half* __restrict__ W1,
              float* __restrict__ C1,
              const __half* __restrict__ A2, const __half* __restrict__ W2,
              float* __restrict__ C2) {
    extern __shared__ char smem[];
    u32 sb = smem_u32(smem);
    const int tid = threadIdx.x, lane = tid & 31, wid = tid >> 5;
    const int bm = blockIdx.y * GBM, bn = blockIdx.x * GBN;
    const int mband = (wid >> 1) * 64, nband = (wid & 1) * 64;

    const __half* A = (blockIdx.z == 0) ? A0 : (blockIdx.z == 1) ? A1 : A2;
    const __half* W = (blockIdx.z == 0) ? W0 : (blockIdx.z == 1) ? W1 : W2;
    float*        C = (blockIdx.z == 0) ? C0 : (blockIdx.z == 1) ? C1 : C2;

    const int arow = lane & 15;
    const int acg  = (lane >> 4) * 16;
    const int brow = ((lane >> 4) & 1) * 8 + (lane & 7);
    const int bcg  = ((lane >> 3) & 1) * 16;

    float acc[4][8][4];
#pragma unroll
    for (int i = 0; i < 4; i++)
#pragma unroll
        for (int j = 0; j < 8; j++)
#pragma unroll
            for (int q = 0; q < 4; q++) acc[i][j][q] = 0.f;

    const __half* Ag = A + (size_t)bm * D_C;
    const __half* Wg = W + (size_t)bn * D_C;

#define ISSUE(kt)                                                              \
    {                                                                          \
        u32 st = sb + ((kt) % 3) * STG;                                        \
        int koff = (kt) * 64;                                                  \
        _Pragma("unroll")                                                      \
        for (int ii = 0; ii < 8; ii++) {                                       \
            int g = tid + (ii << 7);                                           \
            int row = g >> 3, c8 = g & 7;                                      \
            u32 so = SWZ(row * 128 + c8 * 16);                                 \
            cpasync16(st + so,         Ag + (size_t)row * D_C + koff + c8 * 8);\
            cpasync16(st + 16384 + so, Wg + (size_t)row * D_C + koff + c8 * 8);\
        }                                                                      \
        CP_COMMIT;                                                             \
    }

    ISSUE(0); ISSUE(1);
    for (int kt = 0; kt < 16; kt++) {
        if (kt == 15) { CP_WAIT0; } else { CP_WAIT1; }
        __syncthreads();
        if (kt + 2 < 16) ISSUE(kt + 2);

        u32 aB = sb + (kt % 3) * STG;
        u32 bB = aB + 16384;
#pragma unroll
        for (int s = 0; s < 4; s++) {
            u32 af[4][4];
#pragma unroll
            for (int i = 0; i < 4; i++) {
                u32 addr = aB + SWZ((mband + 16 * i + arow) * 128 + s * 32 + acg);
                ldsm4(af[i][0], af[i][1], af[i][2], af[i][3], addr);
            }
#pragma unroll
            for (int jp = 0; jp < 4; jp++) {
                u32 b0, b1, b2, b3;
                u32 addr = bB + SWZ((nband + 16 * jp + brow) * 128 + s * 32 + bcg);
                ldsm4(b0, b1, b2, b3, addr);
#pragma unroll
                for (int i = 0; i < 4; i++) {
                    mma_f16(acc[i][2 * jp],     af[i][0], af[i][1], af[i][2], af[i][3], b0, b1);
                    mma_f16(acc[i][2 * jp + 1], af[i][0], af[i][1], af[i][2], af[i][3], b2, b3);
                }
            }
        }
    }

#pragma unroll
    for (int i = 0; i < 4; i++) {
        int row = bm + mband + 16 * i + (lane >> 2);
#pragma unroll
        for (int j = 0; j < 8; j++) {
            int col = bn + nband + 8 * j + 2 * (lane & 3);
            *(float2*)&C[(size_t)row * D_C + col] =
                make_float2(acc[i][j][0], acc[i][j][1]);
            *(float2*)&C[(size_t)(row + 8) * D_C + col] =
                make_float2(acc[i][j][2], acc[i][j][3]);
        }
    }
}

// ---------------- WKV chunked scan --------------------------------------------
// pass1: per (chain, chunk) compute chunk-local state from zero init.
__global__ void wkv_pass1(const float* __restrict__ w) {
    int g = blockIdx.x * blockDim.x + threadIdx.x;  // 0..131071
    int chain = g & (NCH - 1), s = g >> 13;
    int b = chain >> 10, c = chain & (D_C - 1);
    float wn = -__expf(w[c]);

    size_t base = (size_t)b * N_T * D_C + (size_t)s * LCH * D_C + c;
    const float* kp = g_k + base;
    const float* vp = g_v + base;

    float aa = 0.f, bb = 0.f, pp = -1e38f;
#pragma unroll 4
    for (int j = 0; j < LCH; j++) {
        float kt = kp[(size_t)j * D_C];
        float vt = vp[(size_t)j * D_C];
        float ww2 = pp + wn;
        float p2  = fmaxf(ww2, kt);
        float e1b = __expf(ww2 - p2);
        float e2b = __expf(kt - p2);
        aa = e1b * aa + e2b * vt;
        bb = e1b * bb + e2b;
        pp = p2;
    }
    int o = s * NCH + chain;
    g_saa[o] = aa; g_sbb[o] = bb; g_spp[o] = pp;
}

// pass2: sequential merge over chunks; store incoming state per chunk.
__global__ void wkv_pass2(const float* __restrict__ w) {
    int chain = blockIdx.x * blockDim.x + threadIdx.x;  // 0..8191
    int c = chain & (D_C - 1);
    float wn = -__expf(w[c]);
    float Lwn = (float)LCH * wn;

    float aa = 0.f, bb = 0.f, pp = -1e38f;
#pragma unroll
    for (int s = 0; s < SCH; s++) {
        int o = s * NCH + chain;
        g_iaa[o] = aa; g_ibb[o] = bb; g_ipp[o] = pp;
        float la = g_saa[o], lb = g_sbb[o], lp = g_spp[o];
        float ppa = pp + Lwn;
        float ppm = fmaxf(ppa, lp);
        float e1 = __expf(ppa - ppm);
        float e2 = __expf(lp - ppm);
        aa = e1 * aa + e2 * la;
        bb = e1 * bb + e2 * lb;
        pp = ppm;
    }
}

// pass3: replay each chunk from incoming state, produce gated outputs.
__global__ void wkv_pass3(const float* __restrict__ w,
                          const float* __restrict__ u) {
    int g = blockIdx.x * blockDim.x + threadIdx.x;  // 0..131071
    int chain = g & (NCH - 1), s = g >> 13;
    int b = chain >> 10, c = chain & (D_C - 1);
    float wn = -__expf(w[c]);
    float uc = u[c];

    int o = s * NCH + chain;
    float aa = g_iaa[o], bb = g_ibb[o], pp = g_ipp[o];

    size_t base = (size_t)b * N_T * D_C + (size_t)s * LCH * D_C + c;
    const float* kp = g_k + base;
    const float* vp = g_v + base;
    const float* rp = g_r + base;
    __half*      op = g_rw + base;

#pragma unroll 4
    for (int j = 0; j < LCH; j++) {
        float kt = kp[(size_t)j * D_C];
        float vt = vp[(size_t)j * D_C];
        float rt = rp[(size_t)j * D_C];

        float ww = uc + kt;
        float p  = fmaxf(pp, ww);
        float e1 = __expf(pp - p);
        float e2 = __expf(ww - p);
        float y  = __fdividef(e1 * aa + e2 * vt, e1 * bb + e2);

        float sg = __fdividef(1.f, 1.f + __expf(-rt));
        op[(size_t)j * D_C] = __float2half_rn(y * sg);

        float ww2 = pp + wn;
        float p2  = fmaxf(ww2, kt);
        float e1b = __expf(ww2 - p2);
        float e2b = __expf(kt - p2);
        aa = e1b * aa + e2b * vt;
        bb = e1b * bb + e2b;
        pp = p2;
    }
}

// ---------------- launch ------------------------------------------------------
extern "C" void kernel_launch(void* const* d_in, const int* in_sizes, int n_in,
                              void* d_out, int out_size) {
    const float* x   = (const float*)d_in[0];
    const float* w   = (const float*)d_in[1];
    const float* u   = (const float*)d_in[2];
    const float* tmk = (const float*)d_in[3];
    const float* tmv = (const float*)d_in[4];
    const float* tmr = (const float*)d_in[5];
    const float* Wk  = (const float*)d_in[6];
    const float* Wv  = (const float*)d_in[7];
    const float* Wr  = (const float*)d_in[8];
    const float* Wo  = (const float*)d_in[9];
    float* out = (float*)d_out;

    __half *xk, *xv, *xr, *rw, *wk, *wv, *wr, *wo;
    float *k, *v, *r;
    cudaGetSymbolAddress((void**)&xk, g_xk);
    cudaGetSymbolAddress((void**)&xv, g_xv);
    cudaGetSymbolAddress((void**)&xr, g_xr);
    cudaGetSymbolAddress((void**)&rw, g_rw);
    cudaGetSymbolAddress((void**)&wk, g_wk);
    cudaGetSymbolAddress((void**)&wv, g_wv);
    cudaGetSymbolAddress((void**)&wr, g_wr);
    cudaGetSymbolAddress((void**)&wo, g_wo);
    cudaGetSymbolAddress((void**)&k,  g_k);
    cudaGetSymbolAddress((void**)&v,  g_v);
    cudaGetSymbolAddress((void**)&r,  g_r);

    cudaFuncSetAttribute(gemm_f16,
                         cudaFuncAttributeMaxDynamicSharedMemorySize, GSMEM);

    // 1) fp16 weights + mixed activations
    wconv_kernel<<<dim3(1024, 4), 256>>>((const float4*)Wk, wk,
                                         (const float4*)Wv, wv,
                                         (const float4*)Wr, wr,
                                         (const float4*)Wo, wo);
    mix_kernel<<<(M_TOT * D_C / 4) / 256, 256>>>(x, tmk, tmv, tmr);

    // 2) K/V/R projections in ONE z-batched launch
    dim3 gg3(D_C / GBN, M_TOT / GBM, 3);
    gemm_f16<<<gg3, 128, GSMEM>>>(xk, wk, k, xv, wv, v, xr, wr, r);

    // 3) WKV chunked scan (parallel over SCH chunks) + sigmoid gate
    wkv_pass1<<<(SCH * NCH) / 256, 256>>>(w);
    wkv_pass2<<<NCH / 256, 256>>>(w);
    wkv_pass3<<<(SCH * NCH) / 256, 256>>>(w, u);

    // 4) output projection
    dim3 gg1(D_C / GBN, M_TOT / GBM, 1);
    gemm_f16<<<gg1, 128, GSMEM>>>(rw, wo, out, rw, wo, out, rw, wo, out);
}

// round 12
// speedup vs baseline: 9.0302x; 1.1195x over previous
#include <cuda_runtime.h>
#include <cuda_fp16.h>
#include <stdint.h>

typedef unsigned int u32;
typedef unsigned long long u64;

#define D_C   1024
#define N_T   2048
#define M_TOT 16384   // 8 * 2048
#define NCH   8192    // B * D_C chains
#define SCH   32      // scan chunks
#define LCH   64      // tokens per chunk (SCH*LCH = N_T)

// ---------------- scratch (__device__ globals; no cudaMalloc allowed) ---------
__device__ __half g_xk[(size_t)M_TOT * D_C];
__device__ __half g_xv[(size_t)M_TOT * D_C];
__device__ __half g_xr[(size_t)M_TOT * D_C];
__device__ __half g_rw[(size_t)M_TOT * D_C];
__device__ __half g_k [(size_t)M_TOT * D_C];
__device__ __half g_v [(size_t)M_TOT * D_C];
__device__ __half g_r [(size_t)M_TOT * D_C];
__device__ __half g_wk[(size_t)D_C * D_C];
__device__ __half g_wv[(size_t)D_C * D_C];
__device__ __half g_wr[(size_t)D_C * D_C];
__device__ __half g_wo[(size_t)D_C * D_C];
// chunked-scan state: [SCH][NCH]
__device__ float g_saa[SCH * NCH], g_sbb[SCH * NCH], g_spp[SCH * NCH];
__device__ float g_iaa[SCH * NCH], g_ibb[SCH * NCH], g_ipp[SCH * NCH];

// ---------------- PTX helpers (baseline ISA only) ------------------------------
__device__ __forceinline__ u32 smem_u32(const void* p) {
    u32 a;
    asm("{ .reg .u64 t; cvta.to.shared.u64 t, %1; cvt.u32.u64 %0, t; }"
        : "=r"(a) : "l"(p));
    return a;
}
#define SWZ(o) ((u32)(o) ^ ((((u32)(o)) >> 3) & 0x70))

__device__ __forceinline__ void cpasync16(u32 s, const void* g) {
    asm volatile("cp.async.cg.shared.global [%0], [%1], 16;" :: "r"(s), "l"(g));
}
#define CP_COMMIT asm volatile("cp.async.commit_group;" ::: "memory")
#define CP_WAIT1  asm volatile("cp.async.wait_group 1;" ::: "memory")
#define CP_WAIT0  asm volatile("cp.async.wait_group 0;" ::: "memory")

__device__ __forceinline__ void ldsm4(u32& r0, u32& r1, u32& r2, u32& r3, u32 a) {
    asm volatile("ldmatrix.sync.aligned.m8n8.x4.shared.b16 {%0,%1,%2,%3}, [%4];"
                 : "=r"(r0), "=r"(r1), "=r"(r2), "=r"(r3) : "r"(a));
}

__device__ __forceinline__ void mma_f16(float* d, u32 a0, u32 a1, u32 a2, u32 a3,
                                        u32 b0, u32 b1) {
    asm volatile(
        "mma.sync.aligned.m16n8k16.row.col.f32.f16.f16.f32 "
        "{%0,%1,%2,%3},{%4,%5,%6,%7},{%8,%9},{%0,%1,%2,%3};"
        : "+f"(d[0]), "+f"(d[1]), "+f"(d[2]), "+f"(d[3])
        : "r"(a0), "r"(a1), "r"(a2), "r"(a3), "r"(b0), "r"(b1));
}

__device__ __forceinline__ u32 pack_h2(float lo, float hi) {
    __half2 h = __floats2half2_rn(lo, hi);
    return *(u32*)&h;
}

// epilogue store: fp32 or fp16 output, same call site
__device__ __forceinline__ void st2(float* C, size_t idx, float a, float b) {
    *(float2*)&C[idx] = make_float2(a, b);
}
__device__ __forceinline__ void st2(__half* C, size_t idx, float a, float b) {
    *(__half2*)&C[idx] = __floats2half2_rn(a, b);
}

// ---------------- weight convert: 4 matrices fp32 -> fp16, one launch ---------
__global__ void wconv_kernel(const float4* __restrict__ W0, __half* __restrict__ O0,
                             const float4* __restrict__ W1, __half* __restrict__ O1,
                             const float4* __restrict__ W2, __half* __restrict__ O2,
                             const float4* __restrict__ W3, __half* __restrict__ O3) {
    int i = blockIdx.x * blockDim.x + threadIdx.x;
    const float4* W = (blockIdx.y == 0) ? W0 : (blockIdx.y == 1) ? W1
                    : (blockIdx.y == 2) ? W2 : W3;
    __half* O = (blockIdx.y == 0) ? O0 : (blockIdx.y == 1) ? O1
              : (blockIdx.y == 2) ? O2 : O3;
    float4 v = W[i];
    ((uint2*)O)[i] = make_uint2(pack_h2(v.x, v.y), pack_h2(v.z, v.w));
}

// ---------------- token-shift mix -> fp16 -------------------------------------
__global__ void mix_kernel(const float* __restrict__ x,
                           const float* __restrict__ tmk,
                           const float* __restrict__ tmv,
                           const float* __restrict__ tmr) {
    const int C4 = D_C / 4;
    int i = blockIdx.x * blockDim.x + threadIdx.x;
    int c4 = i & (C4 - 1);
    int bt = i >> 8;
    int t  = bt & (N_T - 1);

    float4 xc = ((const float4*)x)[i];
    float4 xs = make_float4(0.f, 0.f, 0.f, 0.f);
    if (t > 0) xs = ((const float4*)x)[i - C4];

    float4 mk = ((const float4*)tmk)[c4];
    float4 mv = ((const float4*)tmv)[c4];
    float4 mr = ((const float4*)tmr)[c4];

    float kx = xc.x * mk.x + xs.x * (1.f - mk.x);
    float ky = xc.y * mk.y + xs.y * (1.f - mk.y);
    float kz = xc.z * mk.z + xs.z * (1.f - mk.z);
    float kw = xc.w * mk.w + xs.w * (1.f - mk.w);
    float vx = xc.x * mv.x + xs.x * (1.f - mv.x);
    float vy = xc.y * mv.y + xs.y * (1.f - mv.y);
    float vz = xc.z * mv.z + xs.z * (1.f - mv.z);
    float vw = xc.w * mv.w + xs.w * (1.f - mv.w);
    float rx = xc.x * mr.x + xs.x * (1.f - mr.x);
    float ry = xc.y * mr.y + xs.y * (1.f - mr.y);
    float rz = xc.z * mr.z + xs.z * (1.f - mr.z);
    float rw = xc.w * mr.w + xs.w * (1.f - mr.w);

    ((uint2*)g_xk)[i] = make_uint2(pack_h2(kx, ky), pack_h2(kz, kw));
    ((uint2*)g_xv)[i] = make_uint2(pack_h2(vx, vy), pack_h2(vz, vw));
    ((uint2*)g_xr)[i] = make_uint2(pack_h2(rx, ry), pack_h2(rz, rw));
}

// ---------------- fp16 mma.sync GEMM (3-stage pipeline, z-batched) -------------
// C[m,n] = sum_k A[m,k]*W[n,k]; fp16 in, OT out. CTA 128x128, BK=64,
// 3-stage cp.async, one __syncthreads per k-iter. blockIdx.z picks matrix set.
#define GBM 128
#define GBN 128
#define STG 32768                 // per-stage bytes: A 16K + B 16K
#define GSMEM (3 * STG)           // 96 KB

template <typename OT>
__global__ __launch_bounds__(128, 2)
void gemm_f16(const __half* __restrict__ A0, const __half* __restrict__ W0,
              OT* __restrict__ C0,
              const __half* __restrict__ A1, const __half* __restrict__ W1,
              OT* __restrict__ C1,
              const __half* __restrict__ A2, const __half* __restrict__ W2,
              OT* __restrict__ C2) {
    extern __shared__ char smem[];
    u32 sb = smem_u32(smem);
    const int tid = threadIdx.x, lane = tid & 31, wid = tid >> 5;
    const int bm = blockIdx.y * GBM, bn = blockIdx.x * GBN;
    const int mband = (wid >> 1) * 64, nband = (wid & 1) * 64;

    const __half* A = (blockIdx.z == 0) ? A0 : (blockIdx.z == 1) ? A1 : A2;
    const __half* W = (blockIdx.z == 0) ? W0 : (blockIdx.z == 1) ? W1 : W2;
    OT*           C = (blockIdx.z == 0) ? C0 : (blockIdx.z == 1) ? C1 : C2;

    const int arow = lane & 15;
    const int acg  = (lane >> 4) * 16;
    const int brow = ((lane >> 4) & 1) * 8 + (lane & 7);
    const int bcg  = ((lane >> 3) & 1) * 16;

    float acc[4][8][4];
#pragma unroll
    for (int i = 0; i < 4; i++)
#pragma unroll
        for (int j = 0; j < 8; j++)
#pragma unroll
            for (int q = 0; q < 4; q++) acc[i][j][q] = 0.f;

    const __half* Ag = A + (size_t)bm * D_C;
    const __half* Wg = W + (size_t)bn * D_C;

#define ISSUE(kt)                                                              \
    {                                                                          \
        u32 st = sb + ((kt) % 3) * STG;                                        \
        int koff = (kt) * 64;                                                  \
        _Pragma("unroll")                                                      \
        for (int ii = 0; ii < 8; ii++) {                                       \
            int g = tid + (ii << 7);                                           \
            int row = g >> 3, c8 = g & 7;                                      \
            u32 so = SWZ(row * 128 + c8 * 16);                                 \
            cpasync16(st + so,         Ag + (size_t)row * D_C + koff + c8 * 8);\
            cpasync16(st + 16384 + so, Wg + (size_t)row * D_C + koff + c8 * 8);\
        }                                                                      \
        CP_COMMIT;                                                             \
    }

    ISSUE(0); ISSUE(1);
    for (int kt = 0; kt < 16; kt++) {
        if (kt == 15) { CP_WAIT0; } else { CP_WAIT1; }
        __syncthreads();
        if (kt + 2 < 16) ISSUE(kt + 2);

        u32 aB = sb + (kt % 3) * STG;
        u32 bB = aB + 16384;
#pragma unroll
        for (int s = 0; s < 4; s++) {
            u32 af[4][4];
#pragma unroll
            for (int i = 0; i < 4; i++) {
                u32 addr = aB + SWZ((mband + 16 * i + arow) * 128 + s * 32 + acg);
                ldsm4(af[i][0], af[i][1], af[i][2], af[i][3], addr);
            }
#pragma unroll
            for (int jp = 0; jp < 4; jp++) {
                u32 b0, b1, b2, b3;
                u32 addr = bB + SWZ((nband + 16 * jp + brow) * 128 + s * 32 + bcg);
                ldsm4(b0, b1, b2, b3, addr);
#pragma unroll
                for (int i = 0; i < 4; i++) {
                    mma_f16(acc[i][2 * jp],     af[i][0], af[i][1], af[i][2], af[i][3], b0, b1);
                    mma_f16(acc[i][2 * jp + 1], af[i][0], af[i][1], af[i][2], af[i][3], b2, b3);
                }
            }
        }
    }

#pragma unroll
    for (int i = 0; i < 4; i++) {
        int row = bm + mband + 16 * i + (lane >> 2);
#pragma unroll
        for (int j = 0; j < 8; j++) {
            int col = bn + nband + 8 * j + 2 * (lane & 3);
            st2(C, (size_t)row * D_C + col,       acc[i][j][0], acc[i][j][1]);
            st2(C, (size_t)(row + 8) * D_C + col, acc[i][j][2], acc[i][j][3]);
        }
    }
}

// ---------------- WKV chunked scan (fp16 k/v/r IO) ----------------------------
// pass1: per (chain, chunk) compute chunk-local state from zero init.
__global__ void wkv_pass1(const float* __restrict__ w) {
    int g = blockIdx.x * blockDim.x + threadIdx.x;  // 0..SCH*NCH-1
    int chain = g & (NCH - 1), s = g >> 13;
    int b = chain >> 10, c = chain & (D_C - 1);
    float wn = -__expf(w[c]);

    size_t base = (size_t)b * N_T * D_C + (size_t)s * LCH * D_C + c;
    const __half* kp = g_k + base;
    const __half* vp = g_v + base;

    float aa = 0.f, bb = 0.f, pp = -1e38f;
#pragma unroll 8
    for (int j = 0; j < LCH; j++) {
        float kt = __half2float(kp[(size_t)j * D_C]);
        float vt = __half2float(vp[(size_t)j * D_C]);
        float ww2 = pp + wn;
        float p2  = fmaxf(ww2, kt);
        float e1b = __expf(ww2 - p2);
        float e2b = __expf(kt - p2);
        aa = e1b * aa + e2b * vt;
        bb = e1b * bb + e2b;
        pp = p2;
    }
    int o = s * NCH + chain;
    g_saa[o] = aa; g_sbb[o] = bb; g_spp[o] = pp;
}

// pass2: sequential merge over chunks; store incoming state per chunk.
__global__ void wkv_pass2(const float* __restrict__ w) {
    int chain = blockIdx.x * blockDim.x + threadIdx.x;  // 0..NCH-1
    int c = chain & (D_C - 1);
    float wn = -__expf(w[c]);
    float Lwn = (float)LCH * wn;

    float aa = 0.f, bb = 0.f, pp = -1e38f;
#pragma unroll
    for (int s = 0; s < SCH; s++) {
        int o = s * NCH + chain;
        g_iaa[o] = aa; g_ibb[o] = bb; g_ipp[o] = pp;
        float la = g_saa[o], lb = g_sbb[o], lp = g_spp[o];
        float ppa = pp + Lwn;
        float ppm = fmaxf(ppa, lp);
        float e1 = __expf(ppa - ppm);
        float e2 = __expf(lp - ppm);
        aa = e1 * aa + e2 * la;
        bb = e1 * bb + e2 * lb;
        pp = ppm;
    }
}

// pass3: replay each chunk from incoming state, produce gated outputs.
__global__ void wkv_pass3(const float* __restrict__ w,
                          const float* __restrict__ u) {
    int g = blockIdx.x * blockDim.x + threadIdx.x;
    int chain = g & (NCH - 1), s = g >> 13;
    int b = chain >> 10, c = chain & (D_C - 1);
    float wn = -__expf(w[c]);
    float uc = u[c];

    int o = s * NCH + chain;
    float aa = g_iaa[o], bb = g_ibb[o], pp = g_ipp[o];

    size_t base = (size_t)b * N_T * D_C + (size_t)s * LCH * D_C + c;
    const __half* kp = g_k + base;
    const __half* vp = g_v + base;
    const __half* rp = g_r + base;
    __half*       op = g_rw + base;

#pragma unroll 8
    for (int j = 0; j < LCH; j++) {
        float kt = __half2float(kp[(size_t)j * D_C]);
        float vt = __half2float(vp[(size_t)j * D_C]);
        float rt = __half2float(rp[(size_t)j * D_C]);

        float ww = uc + kt;
        float p  = fmaxf(pp, ww);
        float e1 = __expf(pp - p);
        float e2 = __expf(ww - p);
        float y  = __fdividef(e1 * aa + e2 * vt, e1 * bb + e2);

        float sg = __fdividef(1.f, 1.f + __expf(-rt));
        op[(size_t)j * D_C] = __float2half_rn(y * sg);

        float ww2 = pp + wn;
        float p2  = fmaxf(ww2, kt);
        float e1b = __expf(ww2 - p2);
        float e2b = __expf(kt - p2);
        aa = e1b * aa + e2b * vt;
        bb = e1b * bb + e2b;
        pp = p2;
    }
}

// ---------------- launch (single stream — graph-capture safe) -----------------
extern "C" void kernel_launch(void* const* d_in, const int* in_sizes, int n_in,
                              void* d_out, int out_size) {
    const float* x   = (const float*)d_in[0];
    const float* w   = (const float*)d_in[1];
    const float* u   = (const float*)d_in[2];
    const float* tmk = (const float*)d_in[3];
    const float* tmv = (const float*)d_in[4];
    const float* tmr = (const float*)d_in[5];
    const float* Wk  = (const float*)d_in[6];
    const float* Wv  = (const float*)d_in[7];
    const float* Wr  = (const float*)d_in[8];
    const float* Wo  = (const float*)d_in[9];
    float* out = (float*)d_out;

    __half *xk, *xv, *xr, *rw, *wk, *wv, *wr, *wo, *k, *v, *r;
    cudaGetSymbolAddress((void**)&xk, g_xk);
    cudaGetSymbolAddress((void**)&xv, g_xv);
    cudaGetSymbolAddress((void**)&xr, g_xr);
    cudaGetSymbolAddress((void**)&rw, g_rw);
    cudaGetSymbolAddress((void**)&wk, g_wk);
    cudaGetSymbolAddress((void**)&wv, g_wv);
    cudaGetSymbolAddress((void**)&wr, g_wr);
    cudaGetSymbolAddress((void**)&wo, g_wo);
    cudaGetSymbolAddress((void**)&k,  g_k);
    cudaGetSymbolAddress((void**)&v,  g_v);
    cudaGetSymbolAddress((void**)&r,  g_r);

    cudaFuncSetAttribute(gemm_f16<__half>,
                         cudaFuncAttributeMaxDynamicSharedMemorySize, GSMEM);
    cudaFuncSetAttribute(gemm_f16<float>,
                         cudaFuncAttributeMaxDynamicSharedMemorySize, GSMEM);

    // 1) fp16 weights + mixed activations
    wconv_kernel<<<dim3(1024, 4), 256>>>((const float4*)Wk, wk,
                                         (const float4*)Wv, wv,
                                         (const float4*)Wr, wr,
                                         (const float4*)Wo, wo);
    mix_kernel<<<(M_TOT * D_C / 4) / 256, 256>>>(x, tmk, tmv, tmr);

    // 2) K/V/R projections in ONE z-batched launch (fp16 out)
    dim3 gg3(D_C / GBN, M_TOT / GBM, 3);
    gemm_f16<__half><<<gg3, 128, GSMEM>>>(xk, wk, k, xv, wv, v, xr, wr, r);

    // 3) WKV chunked scan (parallel over SCH chunks) + sigmoid gate
    wkv_pass1<<<(SCH * NCH) / 256, 256>>>(w);
    wkv_pass2<<<NCH / 256, 256>>>(w);
    wkv_pass3<<<(SCH * NCH) / 256, 256>>>(w, u);

    // 4) output projection (fp32 out to d_out)
    dim3 gg1(D_C / GBN, M_TOT / GBM, 1);
    gemm_f16<float><<<gg1, 128, GSMEM>>>(rw, wo, out, rw, wo, out, rw, wo, out);
}